// round 10
// baseline (speedup 1.0000x reference)
#include <cuda_runtime.h>
#include <cstdint>

#define SPATIAL 131072   // D*H*W per (batch, channel)
#define HW2     16384    // H*W
#define TW      136      // mid tile row stride (floats)

// Scratch (no allocations allowed anywhere)
__device__ float g_h [2 * 64 * SPATIAL];
__device__ float g_uv[2 * 64 * SPATIAL];
__device__ float g_vp[2 * 3  * SPATIAL];

typedef unsigned long long u64;

__device__ __forceinline__ u64 pack_dup(float x) {
    u64 u; asm("mov.b64 %0, {%1, %2};" : "=l"(u) : "f"(x), "f"(x)); return u;
}
__device__ __forceinline__ u64 pack2(float a, float b) {
    u64 u; asm("mov.b64 %0, {%1, %2};" : "=l"(u) : "f"(a), "f"(b)); return u;
}
__device__ __forceinline__ void fma2(u64& d, u64 a, u64 b) {
    asm("fma.rn.f32x2 %0, %1, %2, %0;" : "+l"(d) : "l"(a), "l"(b));
}
__device__ __forceinline__ float2 unpk(u64 v) {
    float2 f; asm("mov.b64 {%0, %1}, %2;" : "=f"(f.x), "=f"(f.y) : "l"(v)); return f;
}

// bf16 round-to-nearest-even (bits in low 16)
__device__ __forceinline__ uint32_t bf16rn(float x) {
    uint32_t u = __float_as_uint(x);
    return (u + 0x7FFFu + ((u >> 16) & 1u)) >> 16;
}
__device__ __forceinline__ void bf16split4(float4 v, uint2& hi, uint2& lo) {
    uint32_t h0 = bf16rn(v.x), h1 = bf16rn(v.y), h2 = bf16rn(v.z), h3 = bf16rn(v.w);
    float l0 = v.x - __uint_as_float(h0 << 16);
    float l1 = v.y - __uint_as_float(h1 << 16);
    float l2 = v.z - __uint_as_float(h2 << 16);
    float l3 = v.w - __uint_as_float(h3 << 16);
    hi.x = h0 | (h1 << 16); hi.y = h2 | (h3 << 16);
    lo.x = bf16rn(l0) | (bf16rn(l1) << 16);
    lo.y = bf16rn(l2) | (bf16rn(l3) << 16);
}

__device__ __forceinline__ void mma_bf16(float* c, const uint32_t* a,
                                         uint32_t b0, uint32_t b1) {
    asm volatile(
        "mma.sync.aligned.m16n8k16.row.col.f32.bf16.bf16.f32 "
        "{%0,%1,%2,%3}, {%4,%5,%6,%7}, {%8,%9}, {%0,%1,%2,%3};"
        : "+f"(c[0]), "+f"(c[1]), "+f"(c[2]), "+f"(c[3])
        : "r"(a[0]), "r"(a[1]), "r"(a[2]), "r"(a[3]), "r"(b0), "r"(b1));
}

// ---------------------------------------------------------------------------
// Tensor GEMM (mma.sync bf16, 3-term split; R6 logic, wrapper packaging):
//   C[b][oc][p] = sum_ic W[oc][ic] * X[b][ic][p]   (64x64xSPATIAL)
// CTA: 64 x 128 pos. 8 warps; each warp 4 m-tiles x 2 n-tiles x 4 k-tiles.
// smem: Ahi[64][72]bf16 @0, Alo @9216, Bt[128 pos][272B: hi 64ic | lo 64ic] @18432.
// VP_EPI (head): Vp[b][r][p] = sum_oc Vw[oc][r] * C[oc][p] via shfl reduce.
// ---------------------------------------------------------------------------
template<bool VP_EPI>
__device__ __forceinline__ void gemm_mma_body(const float* __restrict__ X,
                                              const float* __restrict__ W,
                                              float* __restrict__ C,
                                              const float* __restrict__ Vw) {
    extern __shared__ char sm[];
    __shared__ float s_vw[192];
    const int t = threadIdx.x, lane = t & 31, warp = t >> 5;
    const int tq = lane & 3, tr = lane >> 2;       // t%4, t/4
    const int b = blockIdx.y;
    const int p0 = blockIdx.x * 128;
    const float* Xb = X + b * 64 * SPATIAL;

    if (VP_EPI && t < 192) s_vw[t] = Vw[t];

    // ---- fill A (64x64 W -> bf16 hi/lo, row-major stride 144B) ----
#pragma unroll
    for (int i = 0; i < 4; ++i) {
        int g = t + 256 * i;                    // 1024 float4 groups
        int row = g >> 4, c4 = (g & 15) * 4;
        float4 v = *reinterpret_cast<const float4*>(W + row * 64 + c4);
        uint2 hi, lo; bf16split4(v, hi, lo);
        *reinterpret_cast<uint2*>(sm + row * 144 + c4 * 2)        = hi;
        *reinterpret_cast<uint2*>(sm + 9216 + row * 144 + c4 * 2) = lo;
    }
    // ---- fill B transposed ([pos][ic] bf16 hi/lo, row stride 272B) ----
#pragma unroll
    for (int i = 0; i < 8; ++i) {
        int g = t + 256 * i;                    // 2048 (pos, ic4) groups
        int pos = g & 127, ic4 = g >> 7;        // ic4: 0..15
        const float* s = Xb + (ic4 * 4) * SPATIAL + p0 + pos;
        float4 v = make_float4(s[0], s[SPATIAL], s[2 * SPATIAL], s[3 * SPATIAL]);
        uint2 hi, lo; bf16split4(v, hi, lo);
        char* rp = sm + 18432 + pos * 272;
        *reinterpret_cast<uint2*>(rp + ic4 * 8)       = hi;
        *reinterpret_cast<uint2*>(rp + 128 + ic4 * 8) = lo;
    }
    __syncthreads();

    float acc[4][2][4];
#pragma unroll
    for (int mt = 0; mt < 4; ++mt)
#pragma unroll
        for (int nt = 0; nt < 2; ++nt)
#pragma unroll
            for (int q = 0; q < 4; ++q) acc[mt][nt][q] = 0.f;

#pragma unroll
    for (int kt = 0; kt < 4; ++kt) {
        uint32_t ah[4][4], al[4][4];
#pragma unroll
        for (int mt = 0; mt < 4; ++mt) {
            int ba = (mt * 16 + tr) * 144 + (kt * 16 + 2 * tq) * 2;
            ah[mt][0] = *reinterpret_cast<const uint32_t*>(sm + ba);
            ah[mt][1] = *reinterpret_cast<const uint32_t*>(sm + ba + 1152);
            ah[mt][2] = *reinterpret_cast<const uint32_t*>(sm + ba + 16);
            ah[mt][3] = *reinterpret_cast<const uint32_t*>(sm + ba + 1168);
            al[mt][0] = *reinterpret_cast<const uint32_t*>(sm + 9216 + ba);
            al[mt][1] = *reinterpret_cast<const uint32_t*>(sm + 9216 + ba + 1152);
            al[mt][2] = *reinterpret_cast<const uint32_t*>(sm + 9216 + ba + 16);
            al[mt][3] = *reinterpret_cast<const uint32_t*>(sm + 9216 + ba + 1168);
        }
        uint32_t bh[2][2], bl[2][2];
#pragma unroll
        for (int nt = 0; nt < 2; ++nt) {
            int bb = 18432 + (warp * 16 + nt * 8 + tr) * 272 + (kt * 16 + 2 * tq) * 2;
            bh[nt][0] = *reinterpret_cast<const uint32_t*>(sm + bb);
            bh[nt][1] = *reinterpret_cast<const uint32_t*>(sm + bb + 16);
            bl[nt][0] = *reinterpret_cast<const uint32_t*>(sm + bb + 128);
            bl[nt][1] = *reinterpret_cast<const uint32_t*>(sm + bb + 144);
        }
#pragma unroll
        for (int mt = 0; mt < 4; ++mt)
#pragma unroll
            for (int nt = 0; nt < 2; ++nt) {
                mma_bf16(acc[mt][nt], ah[mt], bh[nt][0], bh[nt][1]);
                mma_bf16(acc[mt][nt], ah[mt], bl[nt][0], bl[nt][1]);
                mma_bf16(acc[mt][nt], al[mt], bh[nt][0], bh[nt][1]);
            }
    }

    // ---- store C ----
    float* Cb = C + b * 64 * SPATIAL;
#pragma unroll
    for (int mt = 0; mt < 4; ++mt)
#pragma unroll
        for (int nt = 0; nt < 2; ++nt) {
            int row = mt * 16 + tr;
            int col = p0 + warp * 16 + nt * 8 + 2 * tq;
            *reinterpret_cast<float2*>(Cb + row * SPATIAL + col) =
                make_float2(acc[mt][nt][0], acc[mt][nt][1]);
            *reinterpret_cast<float2*>(Cb + (row + 8) * SPATIAL + col) =
                make_float2(acc[mt][nt][2], acc[mt][nt][3]);
        }

    if (VP_EPI) {
#pragma unroll
        for (int r = 0; r < 3; ++r) {
            float w0[4], w1[4];
#pragma unroll
            for (int mt = 0; mt < 4; ++mt) {
                w0[mt] = s_vw[(mt * 16 + tr) * 3 + r];
                w1[mt] = s_vw[(mt * 16 + tr + 8) * 3 + r];
            }
#pragma unroll
            for (int nt = 0; nt < 2; ++nt) {
                float sx = 0.f, sy = 0.f;
#pragma unroll
                for (int mt = 0; mt < 4; ++mt) {
                    sx += w0[mt] * acc[mt][nt][0] + w1[mt] * acc[mt][nt][2];
                    sy += w0[mt] * acc[mt][nt][1] + w1[mt] * acc[mt][nt][3];
                }
                sx += __shfl_xor_sync(0xffffffffu, sx, 4);
                sy += __shfl_xor_sync(0xffffffffu, sy, 4);
                sx += __shfl_xor_sync(0xffffffffu, sx, 8);
                sy += __shfl_xor_sync(0xffffffffu, sy, 8);
                sx += __shfl_xor_sync(0xffffffffu, sx, 16);
                sy += __shfl_xor_sync(0xffffffffu, sy, 16);
                if (tr == 0)
                    *reinterpret_cast<float2*>(
                        g_vp + (b * 3 + r) * SPATIAL + p0 + warp * 16 + nt * 8 + 2 * tq)
                        = make_float2(sx, sy);
            }
        }
    }
}

// Non-templated entry points (required: templated __global__ silently no-ops here)
__global__ void __launch_bounds__(256, 2)
gemm_head(const float* __restrict__ X, const float* __restrict__ W,
          const float* __restrict__ Vw) {
    gemm_mma_body<true>(X, W, g_h, Vw);
}
__global__ void __launch_bounds__(256, 2)
gemm_tail(const float* __restrict__ W, float* __restrict__ C) {
    gemm_mma_body<false>(g_uv, W, C, nullptr);
}

// ---------------------------------------------------------------------------
// Fused middle (R7/R9, UNCHANGED — passed): replicate-pad + depthwise 3x3x3
// (3 ranks) + L2 norm + UV with precomputed Vp.
// CTA = 1 channel x all 8 d x 4 h-rows x 128 w. 512 threads, 2 CTAs/SM.
// ---------------------------------------------------------------------------
__global__ void __launch_bounds__(512, 2) midkernel(const float* __restrict__ Uw) {
    __shared__ __align__(16) float tile[8 * 6 * TW];   // [dz][hy 0..5][j], j = w+1
    __shared__ u64 uws2[81];
    const int t  = threadIdx.x;
    const int h0 = blockIdx.x * 4;
    const int c  = blockIdx.y;
    const int b  = blockIdx.z;
    const float* Hc = g_h + (b * 64 + c) * SPATIAL;

    if (t < 81) uws2[t] = pack_dup(Uw[t]);

    // ---- load halo tile: 48 rows (8 dz x 6 hy) x 130 floats ----
    {
        const int warp = t >> 5, lane = t & 31;
#pragma unroll
        for (int rr = 0; rr < 3; ++rr) {
            int row = warp + rr * 16;          // 0..47
            int dz = row / 6, hy = row - dz * 6;
            int gh = min(max(h0 + hy - 1, 0), 127);
            const float* src = Hc + dz * HW2 + gh * 128;
            float* dst = &tile[row * TW];
#pragma unroll
            for (int q = 0; q < 5; ++q) {
                int j = lane + q * 32;
                if (j < 130) dst[j] = src[min(max(j - 1, 0), 127)];
            }
        }
    }
    __syncthreads();

    const int d  = t >> 6;          // 0..7
    const int wp = t & 63;
    const int w  = wp * 2;          // output pair; tile j=w holds in[w-1]
    const int zb0 = max(d - 1, 0) * 6;
    const int zb1 = d * 6;
    const int zb2 = min(d + 1, 7) * 6;

    u64 acc[4][3];
#pragma unroll
    for (int i = 0; i < 4; ++i)
#pragma unroll
        for (int r = 0; r < 3; ++r) acc[i][r] = 0ull;

#pragma unroll
    for (int kz = 0; kz < 3; ++kz) {
        const int zro = (kz == 0) ? zb0 : ((kz == 1) ? zb1 : zb2);
#pragma unroll
        for (int khy = 0; khy < 3; ++khy) {
            u64 wt[9];
#pragma unroll
            for (int j = 0; j < 9; ++j) wt[j] = uws2[kz * 27 + khy * 9 + j];
#pragma unroll
            for (int i = 0; i < 4; ++i) {       // output row h0 + i
                const float* p = &tile[(zro + i + khy) * TW + w];
                u64 v01 = *reinterpret_cast<const u64*>(p);
                u64 v23 = *reinterpret_cast<const u64*>(p + 2);
                float2 f01 = unpk(v01), f23 = unpk(v23);
                u64 v12 = pack2(f01.y, f23.x);
                fma2(acc[i][0], v01, wt[0]);
                fma2(acc[i][1], v01, wt[1]);
                fma2(acc[i][2], v01, wt[2]);
                fma2(acc[i][0], v12, wt[3]);
                fma2(acc[i][1], v12, wt[4]);
                fma2(acc[i][2], v12, wt[5]);
                fma2(acc[i][0], v23, wt[6]);
                fma2(acc[i][1], v23, wt[7]);
                fma2(acc[i][2], v23, wt[8]);
            }
        }
    }

    // ---- normalize over ranks, contract with Vp, store ----
    float* UVc = g_uv + (b * 64 + c) * SPATIAL;
    const float* vpb0 = g_vp + (b * 3 + 0) * SPATIAL;
    const float* vpb1 = g_vp + (b * 3 + 1) * SPATIAL;
    const float* vpb2 = g_vp + (b * 3 + 2) * SPATIAL;
#pragma unroll
    for (int i = 0; i < 4; ++i) {
        int sp = d * HW2 + (h0 + i) * 128 + w;
        float2 q0 = unpk(acc[i][0]), q1 = unpk(acc[i][1]), q2 = unpk(acc[i][2]);
        float2 w0 = *reinterpret_cast<const float2*>(vpb0 + sp);
        float2 w1 = *reinterpret_cast<const float2*>(vpb1 + sp);
        float2 w2 = *reinterpret_cast<const float2*>(vpb2 + sp);
        float sa = q0.x * q0.x + q1.x * q1.x + q2.x * q2.x;
        float sb = q0.y * q0.y + q1.y * q1.y + q2.y * q2.y;
        float ia = __fdividef(1.0f, 1e-6f + sqrtf(sa));
        float ib = __fdividef(1.0f, 1e-6f + sqrtf(sb));
        float oa = ia * (q0.x * w0.x + q1.x * w1.x + q2.x * w2.x);
        float ob = ib * (q0.y * w0.y + q1.y * w1.y + q2.y * w2.y);
        *reinterpret_cast<float2*>(UVc + sp) = make_float2(oa, ob);
    }
}

// ---------------------------------------------------------------------------
extern "C" void kernel_launch(void* const* d_in, const int* in_sizes, int n_in,
                              void* d_out, int out_size) {
    const float* x      = (const float*)d_in[0];
    const float* head_w = (const float*)d_in[1];
    const float* tail_w = (const float*)d_in[2];
    const float* Uw     = (const float*)d_in[3];
    const float* Vw     = (const float*)d_in[4];
    float* out = (float*)d_out;

    const int SMEM = 53248;   // 18432 (A hi/lo) + 34816 (B)
    cudaFuncSetAttribute(gemm_head, cudaFuncAttributeMaxDynamicSharedMemorySize, SMEM);
    cudaFuncSetAttribute(gemm_tail, cudaFuncAttributeMaxDynamicSharedMemorySize, SMEM);

    dim3 gg(SPATIAL / 128, 2);
    gemm_head<<<gg, 256, SMEM>>>(x, head_w, Vw);       // h + Vp
    midkernel<<<dim3(32, 64, 2), 512>>>(Uw);           // UV
    gemm_tail<<<gg, 256, SMEM>>>(tail_w, out);         // out
}

// round 11
// speedup vs baseline: 1.2744x; 1.2744x over previous
#include <cuda_runtime.h>
#include <cstdint>

#define SPATIAL 131072   // D*H*W per (batch, channel)
#define HW2     16384    // H*W
#define TW      136      // mid tile row stride (floats)

// Scratch (no allocations allowed anywhere)
__device__ float g_h [2 * 64 * SPATIAL];
__device__ float g_uv[2 * 64 * SPATIAL];
__device__ float g_vp[2 * 3  * SPATIAL];

typedef unsigned long long u64;

__device__ __forceinline__ u64 pack_dup(float x) {
    u64 u; asm("mov.b64 %0, {%1, %2};" : "=l"(u) : "f"(x), "f"(x)); return u;
}
__device__ __forceinline__ u64 pack2(float a, float b) {
    u64 u; asm("mov.b64 %0, {%1, %2};" : "=l"(u) : "f"(a), "f"(b)); return u;
}
__device__ __forceinline__ void fma2(u64& d, u64 a, u64 b) {
    asm("fma.rn.f32x2 %0, %1, %2, %0;" : "+l"(d) : "l"(a), "l"(b));
}
__device__ __forceinline__ float2 unpk(u64 v) {
    float2 f; asm("mov.b64 {%0, %1}, %2;" : "=f"(f.x), "=f"(f.y) : "l"(v)); return f;
}

// ---------------------------------------------------------------------------
// High-occupancy f32x2 GEMM: C[b][m][p] = sum_k A[m][k] * X[b][k][p]
// CTA tile 64 x 128, 256 threads, thread tile 8m x 4n.
// smem = 16K(A) + 32K(B) = 48K; launch_bounds(256,4) -> 4 CTAs/SM (50% occ).
// VP_EPI: Vp[b][r][p] = sum_m Vw[m][r] * C[m][p] (head only).
// ---------------------------------------------------------------------------
template<bool VP_EPI>
__device__ __forceinline__ void gemm_body(const float* __restrict__ X,
                                          const float* __restrict__ A,
                                          float* __restrict__ C,
                                          const float* __restrict__ Vw) {
    __shared__ float As[64 * 64];    // As[k*64 + m] = A[m][k]
    __shared__ float Bs[64 * 128];   // Bs[k*128 + c]
    const int t  = threadIdx.x;
    const int b  = blockIdx.y;
    const int p0 = blockIdx.x * 128;
    const float* Xb = X + b * (64 * SPATIAL);

#pragma unroll
    for (int i = 0; i < 4; ++i) {            // A transposed (1024 float4)
        int fl = t + 256 * i;
        int m = fl >> 4, kq = fl & 15;
        float4 v = *reinterpret_cast<const float4*>(A + m * 64 + kq * 4);
        As[(kq * 4 + 0) * 64 + m] = v.x;
        As[(kq * 4 + 1) * 64 + m] = v.y;
        As[(kq * 4 + 2) * 64 + m] = v.z;
        As[(kq * 4 + 3) * 64 + m] = v.w;
    }
#pragma unroll
    for (int i = 0; i < 8; ++i) {            // B tile 64 x 128 (2048 float4)
        int fl = t + 256 * i;
        int k = fl >> 5, cq = fl & 31;
        *reinterpret_cast<float4*>(Bs + k * 128 + cq * 4) =
            *reinterpret_cast<const float4*>(Xb + k * SPATIAL + p0 + cq * 4);
    }
    __syncthreads();

    const int cg = t & 31;      // cols cg*4 .. cg*4+3
    const int rg = t >> 5;      // rows rg*8 .. rg*8+7
    u64 acc[16];
#pragma unroll
    for (int i = 0; i < 16; ++i) acc[i] = 0ull;

#pragma unroll 8
    for (int k = 0; k < 64; ++k) {
        float4 a0 = *reinterpret_cast<const float4*>(As + k * 64 + rg * 8);
        float4 a1 = *reinterpret_cast<const float4*>(As + k * 64 + rg * 8 + 4);
        float4 bv = *reinterpret_cast<const float4*>(Bs + k * 128 + cg * 4);
        u64 bp0 = pack2(bv.x, bv.y), bp1 = pack2(bv.z, bv.w);
        float am[8] = {a0.x, a0.y, a0.z, a0.w, a1.x, a1.y, a1.z, a1.w};
#pragma unroll
        for (int j = 0; j < 8; ++j) {
            u64 aj = pack_dup(am[j]);
            fma2(acc[j * 2 + 0], aj, bp0);
            fma2(acc[j * 2 + 1], aj, bp1);
        }
    }

    float* Cb = C + b * (64 * SPATIAL);
#pragma unroll
    for (int j = 0; j < 8; ++j) {
        float2 lo = unpk(acc[j * 2 + 0]), hi = unpk(acc[j * 2 + 1]);
        *reinterpret_cast<float4*>(Cb + (rg * 8 + j) * SPATIAL + p0 + cg * 4)
            = make_float4(lo.x, lo.y, hi.x, hi.y);
    }

    if (VP_EPI) {
        u64 pvp[3][2];
#pragma unroll
        for (int r = 0; r < 3; ++r) { pvp[r][0] = 0ull; pvp[r][1] = 0ull; }
#pragma unroll
        for (int j = 0; j < 8; ++j) {
            int m = rg * 8 + j;
#pragma unroll
            for (int r = 0; r < 3; ++r) {
                u64 vw = pack_dup(__ldg(&Vw[m * 3 + r]));
                fma2(pvp[r][0], vw, acc[j * 2 + 0]);
                fma2(pvp[r][1], vw, acc[j * 2 + 1]);
            }
        }
        __syncthreads();                      // Bs reads done -> reuse as vred
        float* vred = Bs;                     // [rowg 8][r 3][col 128] = 12KB
#pragma unroll
        for (int r = 0; r < 3; ++r) {
            *reinterpret_cast<float2*>(vred + (rg * 3 + r) * 128 + cg * 4)     = unpk(pvp[r][0]);
            *reinterpret_cast<float2*>(vred + (rg * 3 + r) * 128 + cg * 4 + 2) = unpk(pvp[r][1]);
        }
        __syncthreads();
#pragma unroll
        for (int i = 0; i < 2; ++i) {
            int idx = t + 256 * i;            // 384 outputs
            if (idx < 384) {
                int r = idx >> 7, col = idx & 127;
                float s = 0.f;
#pragma unroll
                for (int g = 0; g < 8; ++g) s += vred[(g * 3 + r) * 128 + col];
                g_vp[(b * 3 + r) * SPATIAL + p0 + col] = s;
            }
        }
    }
}

// Non-templated entry points (templated __global__ silently no-ops under harness)
__global__ void __launch_bounds__(256, 4)
gemm_head(const float* __restrict__ X, const float* __restrict__ A,
          const float* __restrict__ Vw) {
    gemm_body<true>(X, A, g_h, Vw);
}
__global__ void __launch_bounds__(256, 4)
gemm_tail(const float* __restrict__ A, float* __restrict__ C) {
    gemm_body<false>(g_uv, A, C, nullptr);
}

// ---------------------------------------------------------------------------
// Fused middle (R7/R9, UNCHANGED — passed): replicate-pad + depthwise 3x3x3
// (3 ranks) + L2 norm + UV with precomputed Vp.
// CTA = 1 channel x all 8 d x 4 h-rows x 128 w. 512 threads, 2 CTAs/SM.
// ---------------------------------------------------------------------------
__global__ void __launch_bounds__(512, 2) midkernel(const float* __restrict__ Uw) {
    __shared__ __align__(16) float tile[8 * 6 * TW];   // [dz][hy 0..5][j], j = w+1
    __shared__ u64 uws2[81];
    const int t  = threadIdx.x;
    const int h0 = blockIdx.x * 4;
    const int c  = blockIdx.y;
    const int b  = blockIdx.z;
    const float* Hc = g_h + (b * 64 + c) * SPATIAL;

    if (t < 81) uws2[t] = pack_dup(Uw[t]);

    // ---- load halo tile: 48 rows (8 dz x 6 hy) x 130 floats ----
    {
        const int warp = t >> 5, lane = t & 31;
#pragma unroll
        for (int rr = 0; rr < 3; ++rr) {
            int row = warp + rr * 16;          // 0..47
            int dz = row / 6, hy = row - dz * 6;
            int gh = min(max(h0 + hy - 1, 0), 127);
            const float* src = Hc + dz * HW2 + gh * 128;
            float* dst = &tile[row * TW];
#pragma unroll
            for (int q = 0; q < 5; ++q) {
                int j = lane + q * 32;
                if (j < 130) dst[j] = src[min(max(j - 1, 0), 127)];
            }
        }
    }
    __syncthreads();

    const int d  = t >> 6;          // 0..7
    const int wp = t & 63;
    const int w  = wp * 2;          // output pair; tile j=w holds in[w-1]
    const int zb0 = max(d - 1, 0) * 6;
    const int zb1 = d * 6;
    const int zb2 = min(d + 1, 7) * 6;

    u64 acc[4][3];
#pragma unroll
    for (int i = 0; i < 4; ++i)
#pragma unroll
        for (int r = 0; r < 3; ++r) acc[i][r] = 0ull;

#pragma unroll
    for (int kz = 0; kz < 3; ++kz) {
        const int zro = (kz == 0) ? zb0 : ((kz == 1) ? zb1 : zb2);
#pragma unroll
        for (int khy = 0; khy < 3; ++khy) {
            u64 wt[9];
#pragma unroll
            for (int j = 0; j < 9; ++j) wt[j] = uws2[kz * 27 + khy * 9 + j];
#pragma unroll
            for (int i = 0; i < 4; ++i) {       // output row h0 + i
                const float* p = &tile[(zro + i + khy) * TW + w];
                u64 v01 = *reinterpret_cast<const u64*>(p);
                u64 v23 = *reinterpret_cast<const u64*>(p + 2);
                float2 f01 = unpk(v01), f23 = unpk(v23);
                u64 v12 = pack2(f01.y, f23.x);
                fma2(acc[i][0], v01, wt[0]);
                fma2(acc[i][1], v01, wt[1]);
                fma2(acc[i][2], v01, wt[2]);
                fma2(acc[i][0], v12, wt[3]);
                fma2(acc[i][1], v12, wt[4]);
                fma2(acc[i][2], v12, wt[5]);
                fma2(acc[i][0], v23, wt[6]);
                fma2(acc[i][1], v23, wt[7]);
                fma2(acc[i][2], v23, wt[8]);
            }
        }
    }

    // ---- normalize over ranks, contract with Vp, store ----
    float* UVc = g_uv + (b * 64 + c) * SPATIAL;
    const float* vpb0 = g_vp + (b * 3 + 0) * SPATIAL;
    const float* vpb1 = g_vp + (b * 3 + 1) * SPATIAL;
    const float* vpb2 = g_vp + (b * 3 + 2) * SPATIAL;
#pragma unroll
    for (int i = 0; i < 4; ++i) {
        int sp = d * HW2 + (h0 + i) * 128 + w;
        float2 q0 = unpk(acc[i][0]), q1 = unpk(acc[i][1]), q2 = unpk(acc[i][2]);
        float2 w0 = *reinterpret_cast<const float2*>(vpb0 + sp);
        float2 w1 = *reinterpret_cast<const float2*>(vpb1 + sp);
        float2 w2 = *reinterpret_cast<const float2*>(vpb2 + sp);
        float sa = q0.x * q0.x + q1.x * q1.x + q2.x * q2.x;
        float sb = q0.y * q0.y + q1.y * q1.y + q2.y * q2.y;
        float ia = __fdividef(1.0f, 1e-6f + sqrtf(sa));
        float ib = __fdividef(1.0f, 1e-6f + sqrtf(sb));
        float oa = ia * (q0.x * w0.x + q1.x * w1.x + q2.x * w2.x);
        float ob = ib * (q0.y * w0.y + q1.y * w1.y + q2.y * w2.y);
        *reinterpret_cast<float2*>(UVc + sp) = make_float2(oa, ob);
    }
}

// ---------------------------------------------------------------------------
extern "C" void kernel_launch(void* const* d_in, const int* in_sizes, int n_in,
                              void* d_out, int out_size) {
    const float* x      = (const float*)d_in[0];
    const float* head_w = (const float*)d_in[1];
    const float* tail_w = (const float*)d_in[2];
    const float* Uw     = (const float*)d_in[3];
    const float* Vw     = (const float*)d_in[4];
    float* out = (float*)d_out;

    dim3 gg(SPATIAL / 128, 2);
    gemm_head<<<gg, 256>>>(x, head_w, Vw);       // h + Vp
    midkernel<<<dim3(32, 64, 2), 512>>>(Uw);     // UV
    gemm_tail<<<gg, 256>>>(tail_w, out);         // out
}

// round 12
// speedup vs baseline: 1.3814x; 1.0840x over previous
#include <cuda_runtime.h>
#include <cstdint>

#define SPATIAL 131072   // D*H*W per (batch, channel)
#define HW2     16384    // H*W
#define TWM     72       // mid tile row stride (floats)

// Scratch (no allocations allowed anywhere)
__device__ float g_h [2 * 64 * SPATIAL];
__device__ float g_uv[2 * 64 * SPATIAL];
__device__ float g_vp[2 * 3  * SPATIAL];
__device__ float g_wt[2 * 4096];          // pre-transposed weights [k][m]

typedef unsigned long long u64;

__device__ __forceinline__ u64 pack_dup(float x) {
    u64 u; asm("mov.b64 %0, {%1, %2};" : "=l"(u) : "f"(x), "f"(x)); return u;
}
__device__ __forceinline__ u64 pack2(float a, float b) {
    u64 u; asm("mov.b64 %0, {%1, %2};" : "=l"(u) : "f"(a), "f"(b)); return u;
}
__device__ __forceinline__ void fma2(u64& d, u64 a, u64 b) {
    asm("fma.rn.f32x2 %0, %1, %2, %0;" : "+l"(d) : "l"(a), "l"(b));
}
__device__ __forceinline__ float2 unpk(u64 v) {
    float2 f; asm("mov.b64 {%0, %1}, %2;" : "=f"(f.x), "=f"(f.y) : "l"(v)); return f;
}

// ---------------------------------------------------------------------------
// One-time weight transpose: g_wt[sel][k*64+m] = W_sel[m*64+k]. 1 CTA.
// ---------------------------------------------------------------------------
__global__ void wtranspose(const float* __restrict__ hw,
                           const float* __restrict__ tw) {
    const int t = threadIdx.x;
#pragma unroll
    for (int i = 0; i < 16; ++i) {
        int idx = t + 256 * i;            // 0..4095
        int m = idx >> 6, k = idx & 63;
        g_wt[k * 64 + m]        = hw[idx];
        g_wt[4096 + k * 64 + m] = tw[idx];
    }
}

// ---------------------------------------------------------------------------
// f32x2 GEMM: C[b][m][p] = sum_k A[m][k] * X[b][k][p]
// CTA tile 64 x 128, 256 threads, thread tile 8m x 4n, 4 CTAs/SM.
// A fill = linear copy of pre-transposed g_wt (conflict-free).
// VP_EPI: Vp[b][r][p] = sum_m Vw[m][r] * C[m][p] (head only).
// ---------------------------------------------------------------------------
template<bool VP_EPI>
__device__ __forceinline__ void gemm_body(const float* __restrict__ X,
                                          const float* __restrict__ WT,
                                          float* __restrict__ C,
                                          const float* __restrict__ Vw) {
    __shared__ float As[64 * 64];    // [k][m], linear copy of WT
    __shared__ float Bs[64 * 128];   // [k][c]
    const int t  = threadIdx.x;
    const int b  = blockIdx.y;
    const int p0 = blockIdx.x * 128;
    const float* Xb = X + b * (64 * SPATIAL);

#pragma unroll
    for (int i = 0; i < 4; ++i) {            // A: straight 16KB copy
        int u = t + 256 * i;
        *reinterpret_cast<float4*>(As + u * 4) =
            *reinterpret_cast<const float4*>(WT + u * 4);
    }
#pragma unroll
    for (int i = 0; i < 8; ++i) {            // B tile 64 x 128 (2048 float4)
        int fl = t + 256 * i;
        int k = fl >> 5, cq = fl & 31;
        *reinterpret_cast<float4*>(Bs + k * 128 + cq * 4) =
            *reinterpret_cast<const float4*>(Xb + k * SPATIAL + p0 + cq * 4);
    }
    __syncthreads();

    const int cg = t & 31;      // cols cg*4 .. cg*4+3
    const int rg = t >> 5;      // rows rg*8 .. rg*8+7
    u64 acc[16];
#pragma unroll
    for (int i = 0; i < 16; ++i) acc[i] = 0ull;

#pragma unroll 8
    for (int k = 0; k < 64; ++k) {
        float4 a0 = *reinterpret_cast<const float4*>(As + k * 64 + rg * 8);
        float4 a1 = *reinterpret_cast<const float4*>(As + k * 64 + rg * 8 + 4);
        float4 bv = *reinterpret_cast<const float4*>(Bs + k * 128 + cg * 4);
        u64 bp0 = pack2(bv.x, bv.y), bp1 = pack2(bv.z, bv.w);
        float am[8] = {a0.x, a0.y, a0.z, a0.w, a1.x, a1.y, a1.z, a1.w};
#pragma unroll
        for (int j = 0; j < 8; ++j) {
            u64 aj = pack_dup(am[j]);
            fma2(acc[j * 2 + 0], aj, bp0);
            fma2(acc[j * 2 + 1], aj, bp1);
        }
    }

    float* Cb = C + b * (64 * SPATIAL);
#pragma unroll
    for (int j = 0; j < 8; ++j) {
        float2 lo = unpk(acc[j * 2 + 0]), hi = unpk(acc[j * 2 + 1]);
        *reinterpret_cast<float4*>(Cb + (rg * 8 + j) * SPATIAL + p0 + cg * 4)
            = make_float4(lo.x, lo.y, hi.x, hi.y);
    }

    if (VP_EPI) {
        u64 pvp[3][2];
#pragma unroll
        for (int r = 0; r < 3; ++r) { pvp[r][0] = 0ull; pvp[r][1] = 0ull; }
#pragma unroll
        for (int j = 0; j < 8; ++j) {
            int m = rg * 8 + j;
#pragma unroll
            for (int r = 0; r < 3; ++r) {
                u64 vw = pack_dup(__ldg(&Vw[m * 3 + r]));
                fma2(pvp[r][0], vw, acc[j * 2 + 0]);
                fma2(pvp[r][1], vw, acc[j * 2 + 1]);
            }
        }
        __syncthreads();                      // Bs reads done -> reuse as vred
        float* vred = Bs;                     // [rowg 8][r 3][col 128] = 12KB
#pragma unroll
        for (int r = 0; r < 3; ++r) {
            *reinterpret_cast<float2*>(vred + (rg * 3 + r) * 128 + cg * 4)     = unpk(pvp[r][0]);
            *reinterpret_cast<float2*>(vred + (rg * 3 + r) * 128 + cg * 4 + 2) = unpk(pvp[r][1]);
        }
        __syncthreads();
#pragma unroll
        for (int i = 0; i < 2; ++i) {
            int idx = t + 256 * i;            // 384 outputs
            if (idx < 384) {
                int r = idx >> 7, col = idx & 127;
                float s = 0.f;
#pragma unroll
                for (int g = 0; g < 8; ++g) s += vred[(g * 3 + r) * 128 + col];
                g_vp[(b * 3 + r) * SPATIAL + p0 + col] = s;
            }
        }
    }
}

// Non-templated entry points (templated __global__ silently no-ops under harness)
__global__ void __launch_bounds__(256, 4)
gemm_head(const float* __restrict__ X, const float* __restrict__ Vw) {
    gemm_body<true>(X, g_wt, g_h, Vw);
}
__global__ void __launch_bounds__(256, 4)
gemm_tail(float* __restrict__ C) {
    gemm_body<false>(g_uv, g_wt + 4096, C, nullptr);
}

// ---------------------------------------------------------------------------
// Fused middle: replicate-pad + depthwise 3x3x3 (3 ranks) + L2 norm + UV
// with precomputed Vp. Same per-thread code as R7/R9/R11, retiled:
// CTA = 1 channel x all 8 d x 4 h-rows x 64 w. 256 threads, 4 CTAs/SM.
// ---------------------------------------------------------------------------
__global__ void __launch_bounds__(256, 4) midkernel(const float* __restrict__ Uw) {
    __shared__ __align__(16) float tile[8 * 6 * TWM];  // 48 rows x 72 (j = w-w0+1)
    __shared__ u64 uws2[81];
    const int t  = threadIdx.x;
    const int bx = blockIdx.x;
    const int h0 = (bx >> 1) * 4;
    const int w0 = (bx & 1) * 64;
    const int c  = blockIdx.y;
    const int b  = blockIdx.z;
    const float* Hc = g_h + (b * 64 + c) * SPATIAL;

    if (t < 81) uws2[t] = pack_dup(Uw[t]);

    // ---- load halo tile: 48 rows (8 dz x 6 hy) x 66 floats ----
    {
        const int warp = t >> 5, lane = t & 31;
#pragma unroll
        for (int rr = 0; rr < 6; ++rr) {
            int row = warp + rr * 8;           // 0..47
            int dz = row / 6, hy = row - dz * 6;
            int gh = min(max(h0 + hy - 1, 0), 127);
            const float* src = Hc + dz * HW2 + gh * 128;
            float* dst = &tile[row * TWM];
#pragma unroll
            for (int q = 0; q < 3; ++q) {
                int j = lane + q * 32;
                if (j < 66) dst[j] = src[min(max(w0 - 1 + j, 0), 127)];
            }
        }
    }
    __syncthreads();

    const int d  = t >> 5;          // 0..7
    const int wp = t & 31;
    const int w  = wp * 2;          // local pair; tile j=w holds in[w0+w-1]
    const int zb0 = max(d - 1, 0) * 6;
    const int zb1 = d * 6;
    const int zb2 = min(d + 1, 7) * 6;

    u64 acc[4][3];
#pragma unroll
    for (int i = 0; i < 4; ++i)
#pragma unroll
        for (int r = 0; r < 3; ++r) acc[i][r] = 0ull;

#pragma unroll
    for (int kz = 0; kz < 3; ++kz) {
        const int zro = (kz == 0) ? zb0 : ((kz == 1) ? zb1 : zb2);
#pragma unroll
        for (int khy = 0; khy < 3; ++khy) {
            u64 wt[9];
#pragma unroll
            for (int j = 0; j < 9; ++j) wt[j] = uws2[kz * 27 + khy * 9 + j];
#pragma unroll
            for (int i = 0; i < 4; ++i) {       // output row h0 + i
                const float* p = &tile[(zro + i + khy) * TWM + w];
                u64 v01 = *reinterpret_cast<const u64*>(p);
                u64 v23 = *reinterpret_cast<const u64*>(p + 2);
                float2 f01 = unpk(v01), f23 = unpk(v23);
                u64 v12 = pack2(f01.y, f23.x);
                fma2(acc[i][0], v01, wt[0]);
                fma2(acc[i][1], v01, wt[1]);
                fma2(acc[i][2], v01, wt[2]);
                fma2(acc[i][0], v12, wt[3]);
                fma2(acc[i][1], v12, wt[4]);
                fma2(acc[i][2], v12, wt[5]);
                fma2(acc[i][0], v23, wt[6]);
                fma2(acc[i][1], v23, wt[7]);
                fma2(acc[i][2], v23, wt[8]);
            }
        }
    }

    // ---- normalize over ranks, contract with Vp, store ----
    float* UVc = g_uv + (b * 64 + c) * SPATIAL;
    const float* vpb0 = g_vp + (b * 3 + 0) * SPATIAL;
    const float* vpb1 = g_vp + (b * 3 + 1) * SPATIAL;
    const float* vpb2 = g_vp + (b * 3 + 2) * SPATIAL;
#pragma unroll
    for (int i = 0; i < 4; ++i) {
        int sp = d * HW2 + (h0 + i) * 128 + w0 + w;
        float2 q0 = unpk(acc[i][0]), q1 = unpk(acc[i][1]), q2 = unpk(acc[i][2]);
        float2 w0v = *reinterpret_cast<const float2*>(vpb0 + sp);
        float2 w1v = *reinterpret_cast<const float2*>(vpb1 + sp);
        float2 w2v = *reinterpret_cast<const float2*>(vpb2 + sp);
        float sa = q0.x * q0.x + q1.x * q1.x + q2.x * q2.x;
        float sb = q0.y * q0.y + q1.y * q1.y + q2.y * q2.y;
        float ia = __fdividef(1.0f, 1e-6f + sqrtf(sa));
        float ib = __fdividef(1.0f, 1e-6f + sqrtf(sb));
        float oa = ia * (q0.x * w0v.x + q1.x * w1v.x + q2.x * w2v.x);
        float ob = ib * (q0.y * w0v.y + q1.y * w1v.y + q2.y * w2v.y);
        *reinterpret_cast<float2*>(UVc + sp) = make_float2(oa, ob);
    }
}

// ---------------------------------------------------------------------------
extern "C" void kernel_launch(void* const* d_in, const int* in_sizes, int n_in,
                              void* d_out, int out_size) {
    const float* x      = (const float*)d_in[0];
    const float* head_w = (const float*)d_in[1];
    const float* tail_w = (const float*)d_in[2];
    const float* Uw     = (const float*)d_in[3];
    const float* Vw     = (const float*)d_in[4];
    float* out = (float*)d_out;

    dim3 gg(SPATIAL / 128, 2);
    wtranspose<<<1, 256>>>(head_w, tail_w);      // W -> g_wt (k-major)
    gemm_head<<<gg, 256>>>(x, Vw);               // h + Vp
    midkernel<<<dim3(64, 64, 2), 256>>>(Uw);     // UV
    gemm_tail<<<gg, 256>>>(out);                 // out
}